// round 8
// baseline (speedup 1.0000x reference)
#include <cuda_runtime.h>
#include <cuda_fp16.h>
#include <math_constants.h>
#include <cstdint>

// FixedMoiraiGating: logits = x @ W^T + b ; top-2 ; softmax over the 2 vals.
// x: [8192, 4096] f32, W: [64, 4096] f32, b: [64] f32
// out f32[32768]: [0,16384) = probs; [16384,32768) = indices as float.
//
// Warp-level mma.sync m16n8k16 (plain sm_100 target), fp16 hi/lo 3-term split
// (hh + hl + lh), fp32 accum. R8 = R7 resubmit (infra flake): 16 warps/CTA
// (4/SMSP), warp tile m16 x n32; topk uses 4 lanes/token + shfl merge.

#define D_DIM  4096
#define E_DIM  64
#define BM     128
#define KHALF  2048
#define KC     64
#define NS     (KHALF / KC)
#define NKS    (KHALF / 16)
#define NTOK   8192

__device__ float g_scratch[2 * NTOK * E_DIM];

#define MMA16816(c, a0, a1, a2, a3, b0, b1) \
    asm volatile("mma.sync.aligned.m16n8k16.row.col.f32.f16.f16.f32 " \
                 "{%0,%1,%2,%3}, {%4,%5,%6,%7}, {%8,%9}, {%0,%1,%2,%3};" \
                 : "+f"((c)[0]), "+f"((c)[1]), "+f"((c)[2]), "+f"((c)[3]) \
                 : "r"(a0), "r"(a1), "r"(a2), "r"(a3), "r"(b0), "r"(b1))

#define LDSM_X4(r0, r1, r2, r3, addr) \
    asm volatile("ldmatrix.sync.aligned.m8n8.x4.shared.b16 {%0,%1,%2,%3}, [%4];" \
                 : "=r"(r0), "=r"(r1), "=r"(r2), "=r"(r3) : "r"(addr))

static __device__ __forceinline__ uint32_t smem_u32(const void* p) {
    uint32_t a;
    asm("{ .reg .u64 t; cvta.to.shared.u64 t, %1; cvt.u32.u64 %0, t; }"
        : "=r"(a) : "l"(p));
    return a;
}

static __device__ __forceinline__ uint32_t h2u(__half2 h) {
    return *reinterpret_cast<uint32_t*>(&h);
}

static __device__ __forceinline__ void split2(float2 v, uint32_t& hi, uint32_t& lo) {
    __half2 h = __floats2half2_rn(v.x, v.y);
    float2 bk = __half22float2(h);
    __half2 l = __floats2half2_rn(v.x - bk.x, v.y - bk.y);
    hi = h2u(h);
    lo = h2u(l);
}

static __device__ __forceinline__ uint32_t bswz(int n, uint32_t kbyte) {
    return (uint32_t)(n * 128) + (kbyte ^ (uint32_t)((n & 7) << 4));
}

__global__ __launch_bounds__(512, 1)
void moirai_gemm_kernel(const float* __restrict__ x,
                        const float* __restrict__ W)
{
    __shared__ __align__(1024) uint8_t sBh[2][8192];
    __shared__ __align__(1024) uint8_t sBl[2][8192];

    const int t    = threadIdx.x;
    const int w    = t >> 5;          // 0..15
    const int lane = t & 31;
    const int mi   = w & 7;           // m-tile (m16)
    const int nh   = w >> 3;          // n-half (n32 = 4 nt)
    const int tq   = lane >> 2;
    const int tr   = lane & 3;
    const int mt   = blockIdx.x & 63;
    const int kh   = blockIdx.x >> 6;
    const int tok0 = mt * BM;
    const int kb   = kh * KHALF;

    const uint32_t bh0 = smem_u32(&sBh[0][0]);
    const uint32_t bh1 = smem_u32(&sBh[1][0]);
    const uint32_t bl0 = smem_u32(&sBl[0][0]);
    const uint32_t bl1 = smem_u32(&sBl[1][0]);

    const int t7 = lane & 7;
    const int j  = lane >> 3;
    const int jp = j & 1;
    const int jh = j >> 1;
    const uint32_t lanePart = (uint32_t)(jh * 1024 + t7 * 128);
    const uint32_t xorTerm  = (uint32_t)(t7 << 4);

    float acc[4][4];
#pragma unroll
    for (int nt = 0; nt < 4; nt++)
#pragma unroll
        for (int c = 0; c < 4; c++) acc[nt][c] = 0.0f;

    const int rA = tok0 + mi * 16 + tq;

    float2 af[2][4];
#define LOAD_A(slot, g) do {                                            \
        int kc_ = kb + (g) * 16 + 2 * tr;                               \
        const float* p0_ = x + (size_t)rA * D_DIM + kc_;                \
        const float* p1_ = x + (size_t)(rA + 8) * D_DIM + kc_;          \
        af[slot][0] = *reinterpret_cast<const float2*>(p0_);            \
        af[slot][1] = *reinterpret_cast<const float2*>(p0_ + 8);        \
        af[slot][2] = *reinterpret_cast<const float2*>(p1_);            \
        af[slot][3] = *reinterpret_cast<const float2*>(p1_ + 8);        \
    } while (0)

    // B staging: 1024 float4/stage over 512 threads -> 2 per thread
    float4 bf4[2];
    int   brow[2], bc4[2];
#pragma unroll
    for (int i = 0; i < 2; i++) {
        int p = t + i * 512;
        brow[i] = p >> 4;
        bc4[i]  = p & 15;
    }

#pragma unroll
    for (int i = 0; i < 2; i++)
        bf4[i] = *reinterpret_cast<const float4*>(
            W + (size_t)brow[i] * D_DIM + kb + bc4[i] * 4);
    LOAD_A(0, 0);
    LOAD_A(1, 1);
#pragma unroll
    for (int i = 0; i < 2; i++) {
        uint32_t h0, l0, h1, l1;
        split2(make_float2(bf4[i].x, bf4[i].y), h0, l0);
        split2(make_float2(bf4[i].z, bf4[i].w), h1, l1);
        uint32_t off = bswz(brow[i], (uint32_t)(bc4[i] * 8));
        asm volatile("st.shared.v2.b32 [%0], {%1,%2};" :: "r"(bh0 + off), "r"(h0), "r"(h1) : "memory");
        asm volatile("st.shared.v2.b32 [%0], {%1,%2};" :: "r"(bl0 + off), "r"(l0), "r"(l1) : "memory");
    }
    __syncthreads();

    for (int stage = 0; stage < NS; stage++) {
        const uint32_t curh = (stage & 1) ? bh1 : bh0;
        const uint32_t curl = (stage & 1) ? bl1 : bl0;
        const uint32_t nxth = (stage & 1) ? bh0 : bh1;
        const uint32_t nxtl = (stage & 1) ? bl0 : bl1;

        if (stage + 1 < NS) {
            const int kbs = kb + (stage + 1) * KC;
#pragma unroll
            for (int i = 0; i < 2; i++)
                bf4[i] = *reinterpret_cast<const float4*>(
                    W + (size_t)brow[i] * D_DIM + kbs + bc4[i] * 4);
        }

#pragma unroll
        for (int ks = 0; ks < 4; ks++) {
            const int g = stage * 4 + ks;
            const int slot = g & 1;

            // ldmatrix: this warp's 4 n-tiles (q = nh*4 .. nh*4+3)
            uint32_t bhf[4][2], blf[4][2];
            const uint32_t kpart = ((uint32_t)(ks << 5) | (uint32_t)(jp << 4)) ^ xorTerm;
#pragma unroll
            for (int qq = 0; qq < 4; qq += 2) {
                const int q = nh * 4 + qq;
                uint32_t ah_ = curh + (uint32_t)(q * 1024) + lanePart + kpart;
                uint32_t al_ = curl + (uint32_t)(q * 1024) + lanePart + kpart;
                LDSM_X4(bhf[qq][0], bhf[qq][1], bhf[qq + 1][0], bhf[qq + 1][1], ah_);
                LDSM_X4(blf[qq][0], blf[qq][1], blf[qq + 1][0], blf[qq + 1][1], al_);
            }

            uint32_t ah[4], al[4];
#pragma unroll
            for (int jj = 0; jj < 4; jj++)
                split2(af[slot][jj], ah[jj], al[jj]);

            if (g + 2 < NKS) LOAD_A(slot, g + 2);

#pragma unroll
            for (int nt = 0; nt < 4; nt++) {
                MMA16816(acc[nt], ah[0], ah[2], ah[1], ah[3], bhf[nt][0], bhf[nt][1]);
                MMA16816(acc[nt], ah[0], ah[2], ah[1], ah[3], blf[nt][0], blf[nt][1]);
                MMA16816(acc[nt], al[0], al[2], al[1], al[3], bhf[nt][0], bhf[nt][1]);
            }
        }

        if (stage + 1 < NS) {
#pragma unroll
            for (int i = 0; i < 2; i++) {
                uint32_t h0, l0, h1, l1;
                split2(make_float2(bf4[i].x, bf4[i].y), h0, l0);
                split2(make_float2(bf4[i].z, bf4[i].w), h1, l1);
                uint32_t off = bswz(brow[i], (uint32_t)(bc4[i] * 8));
                asm volatile("st.shared.v2.b32 [%0], {%1,%2};" :: "r"(nxth + off), "r"(h0), "r"(h1) : "memory");
                asm volatile("st.shared.v2.b32 [%0], {%1,%2};" :: "r"(nxtl + off), "r"(l0), "r"(l1) : "memory");
            }
        }
        __syncthreads();
    }

    // epilogue
    float* sbase = g_scratch + (size_t)kh * NTOK * E_DIM;
#pragma unroll
    for (int nt = 0; nt < 4; nt++) {
        int col = nh * 32 + nt * 8 + 2 * tr;
        *reinterpret_cast<float2*>(sbase + (size_t)rA * E_DIM + col) =
            make_float2(acc[nt][0], acc[nt][1]);
        *reinterpret_cast<float2*>(sbase + (size_t)(rA + 8) * E_DIM + col) =
            make_float2(acc[nt][2], acc[nt][3]);
    }
}

// ---- combine + bias + top-2 + softmax: 4 lanes per token ----
__global__ __launch_bounds__(256, 4)
void moirai_topk_kernel(const float* __restrict__ b,
                        float* __restrict__ out)
{
    const int gid  = blockIdx.x * 256 + threadIdx.x;
    const int tok  = gid >> 2;
    const int r    = gid & 3;        // lane's quarter: experts [r*16, r*16+16)

    const float* r0 = g_scratch + (size_t)tok * E_DIM + r * 16;
    const float* r1 = g_scratch + ((size_t)NTOK + tok) * E_DIM + r * 16;
    const float* bb = b + r * 16;

    float v1 = -CUDART_INF_F, v2 = -CUDART_INF_F;
    int i1 = 0, i2 = 0;
#pragma unroll
    for (int g = 0; g < 4; g++) {
        float4 a  = *reinterpret_cast<const float4*>(r0 + g * 4);
        float4 c  = *reinterpret_cast<const float4*>(r1 + g * 4);
        float4 bv = *reinterpret_cast<const float4*>(bb + g * 4);
        float v[4] = {a.x + c.x + bv.x, a.y + c.y + bv.y,
                      a.z + c.z + bv.z, a.w + c.w + bv.w};
#pragma unroll
        for (int jj = 0; jj < 4; jj++) {
            int e = r * 16 + g * 4 + jj;
            if (v[jj] > v1)      { v2 = v1; i2 = i1; v1 = v[jj]; i1 = e; }
            else if (v[jj] > v2) { v2 = v[jj]; i2 = e; }
        }
    }

    // merge top-2 across the 4 lanes of this token (bfly 1, then 2)
#pragma unroll
    for (int m = 1; m <= 2; m <<= 1) {
        float V1 = __shfl_xor_sync(0xFFFFFFFFu, v1, m);
        float V2 = __shfl_xor_sync(0xFFFFFFFFu, v2, m);
        int   I1 = __shfl_xor_sync(0xFFFFFFFFu, i1, m);
        int   I2 = __shfl_xor_sync(0xFFFFFFFFu, i2, m);
        // ensure (v1,i1) is the better set-leader (tie -> lower index)
        if (V1 > v1 || (V1 == v1 && I1 < i1)) {
            float tv; int ti;
            tv = v1; v1 = V1; V1 = tv;  ti = i1; i1 = I1; I1 = ti;
            tv = v2; v2 = V2; V2 = tv;  ti = i2; i2 = I2; I2 = ti;
        }
        // runner-up: best of (v2) vs loser-set leader (V1)
        if (V1 > v2 || (V1 == v2 && I1 < i2)) { v2 = V1; i2 = I1; }
    }

    if (r == 0) {
        float ex  = expf(v2 - v1);
        float inv = 1.0f / (1.0f + ex);
        out[tok * 2 + 0] = inv;
        out[tok * 2 + 1] = ex * inv;
        float* idx_out = out + (size_t)NTOK * 2;
        idx_out[tok * 2 + 0] = (float)i1;
        idx_out[tok * 2 + 1] = (float)i2;
    }
}

extern "C" void kernel_launch(void* const* d_in, const int* in_sizes, int n_in,
                              void* d_out, int out_size)
{
    const float* x = (const float*)d_in[0];
    const float* W = (const float*)d_in[1];
    const float* b = (const float*)d_in[2];
    float* out = (float*)d_out;

    moirai_gemm_kernel<<<128, 512>>>(x, W);
    moirai_topk_kernel<<<(NTOK * 4) / 256, 256>>>(b, out);
}

// round 9
// speedup vs baseline: 1.3614x; 1.3614x over previous
#include <cuda_runtime.h>
#include <cuda_fp16.h>
#include <math_constants.h>
#include <cstdint>

// FixedMoiraiGating: logits = x @ W^T + b ; top-2 ; softmax over the 2 vals.
// x: [8192, 4096] f32, W: [64, 4096] f32, b: [64] f32
// out f32[32768]: [0,16384) = probs; [16384,32768) = indices as float.
//
// mma.sync m16n8k16 fp16 hi/lo 3-term split (hh+hl+lh), fp32 accum.
// R9: intra-CTA split-K. 512 thr: warps 0-7 -> K[0,1024), warps 8-15 ->
// K[1024,2048) of this CTA's K-half. Each warp: unique m16, n64 (no A dup).
// Final smem reduction combines the two groups. topk: 4 lanes/token.

#define D_DIM  4096
#define E_DIM  64
#define BM     128
#define KHALF  2048
#define KGRP   1024           // K per warp-group
#define KC     64             // f32 k per B stage
#define NSG    (KGRP / KC)    // 16 stages per group
#define NKG    (KGRP / 16)    // 64 ksteps per group
#define NTOK   8192

// dynamic smem: per group g (0/1): Bh db0/db1, Bl db0/db1 (8KB each)
#define GB(g)      ((g) * 32768)
#define BH(g, d)   (GB(g) + (d) * 8192)
#define BL(g, d)   (GB(g) + 16384 + (d) * 8192)
#define SMEM_ALLOC (65536 + 1024)

__device__ float g_scratch[2 * NTOK * E_DIM];

#define MMA16816(c, a0, a1, a2, a3, b0, b1) \
    asm volatile("mma.sync.aligned.m16n8k16.row.col.f32.f16.f16.f32 " \
                 "{%0,%1,%2,%3}, {%4,%5,%6,%7}, {%8,%9}, {%0,%1,%2,%3};" \
                 : "+f"((c)[0]), "+f"((c)[1]), "+f"((c)[2]), "+f"((c)[3]) \
                 : "r"(a0), "r"(a1), "r"(a2), "r"(a3), "r"(b0), "r"(b1))

#define LDSM_X4(r0, r1, r2, r3, addr) \
    asm volatile("ldmatrix.sync.aligned.m8n8.x4.shared.b16 {%0,%1,%2,%3}, [%4];" \
                 : "=r"(r0), "=r"(r1), "=r"(r2), "=r"(r3) : "r"(addr))

static __device__ __forceinline__ uint32_t smem_u32(const void* p) {
    uint32_t a;
    asm("{ .reg .u64 t; cvta.to.shared.u64 t, %1; cvt.u32.u64 %0, t; }"
        : "=r"(a) : "l"(p));
    return a;
}

static __device__ __forceinline__ uint32_t h2u(__half2 h) {
    return *reinterpret_cast<uint32_t*>(&h);
}

static __device__ __forceinline__ void split2(float2 v, uint32_t& hi, uint32_t& lo) {
    __half2 h = __floats2half2_rn(v.x, v.y);
    float2 bk = __half22float2(h);
    __half2 l = __floats2half2_rn(v.x - bk.x, v.y - bk.y);
    hi = h2u(h);
    lo = h2u(l);
}

static __device__ __forceinline__ uint32_t bswz(int n, uint32_t kbyte) {
    return (uint32_t)(n * 128) + (kbyte ^ (uint32_t)((n & 7) << 4));
}

__global__ __launch_bounds__(512, 1)
void moirai_gemm_kernel(const float* __restrict__ x,
                        const float* __restrict__ W)
{
    extern __shared__ uint8_t smem_raw[];
    const uint32_t base = (smem_u32(smem_raw) + 1023u) & ~1023u;

    const int t    = threadIdx.x;
    const int w    = t >> 5;          // 0..15
    const int lane = t & 31;
    const int gi   = w >> 3;          // K-group 0/1
    const int wg   = w & 7;           // m-tile within group
    const int tg   = t & 255;         // thread id within group
    const int tq   = lane >> 2;
    const int tr   = lane & 3;
    const int mt   = blockIdx.x & 63;
    const int kh   = blockIdx.x >> 6;
    const int tok0 = mt * BM;
    const int kbg  = kh * KHALF + gi * KGRP;

    const uint32_t bh0 = base + BH(gi, 0);
    const uint32_t bh1 = base + BH(gi, 1);
    const uint32_t bl0 = base + BL(gi, 0);
    const uint32_t bl1 = base + BL(gi, 1);

    const int t7 = lane & 7;
    const int j  = lane >> 3;
    const int jp = j & 1;
    const int jh = j >> 1;
    const uint32_t lanePart = (uint32_t)(jh * 1024 + t7 * 128);
    const uint32_t xorTerm  = (uint32_t)(t7 << 4);

    float acc[8][4];
#pragma unroll
    for (int nt = 0; nt < 8; nt++)
#pragma unroll
        for (int c = 0; c < 4; c++) acc[nt][c] = 0.0f;

    const int rA = tok0 + wg * 16 + tq;

    float2 af[2][4];
#define LOAD_A(slot, g) do {                                            \
        int kc_ = kbg + (g) * 16 + 2 * tr;                              \
        const float* p0_ = x + (size_t)rA * D_DIM + kc_;                \
        const float* p1_ = x + (size_t)(rA + 8) * D_DIM + kc_;          \
        af[slot][0] = *reinterpret_cast<const float2*>(p0_);            \
        af[slot][1] = *reinterpret_cast<const float2*>(p0_ + 8);        \
        af[slot][2] = *reinterpret_cast<const float2*>(p1_);            \
        af[slot][3] = *reinterpret_cast<const float2*>(p1_ + 8);        \
    } while (0)

    // B staging: per group, 1024 float4/stage over 256 threads -> 4/thread
    float4 bf4[4];
    int   brow[4], bc4[4];
#pragma unroll
    for (int i = 0; i < 4; i++) {
        int p = tg + i * 256;
        brow[i] = p >> 4;
        bc4[i]  = p & 15;
    }

    // preload B stage 0 + A ksteps 0,1
#pragma unroll
    for (int i = 0; i < 4; i++)
        bf4[i] = *reinterpret_cast<const float4*>(
            W + (size_t)brow[i] * D_DIM + kbg + bc4[i] * 4);
    LOAD_A(0, 0);
    LOAD_A(1, 1);
#pragma unroll
    for (int i = 0; i < 4; i++) {
        uint32_t h0, l0, h1, l1;
        split2(make_float2(bf4[i].x, bf4[i].y), h0, l0);
        split2(make_float2(bf4[i].z, bf4[i].w), h1, l1);
        uint32_t off = bswz(brow[i], (uint32_t)(bc4[i] * 8));
        asm volatile("st.shared.v2.b32 [%0], {%1,%2};" :: "r"(bh0 + off), "r"(h0), "r"(h1) : "memory");
        asm volatile("st.shared.v2.b32 [%0], {%1,%2};" :: "r"(bl0 + off), "r"(l0), "r"(l1) : "memory");
    }
    __syncthreads();

    for (int stage = 0; stage < NSG; stage++) {
        const uint32_t curh = (stage & 1) ? bh1 : bh0;
        const uint32_t curl = (stage & 1) ? bl1 : bl0;
        const uint32_t nxth = (stage & 1) ? bh0 : bh1;
        const uint32_t nxtl = (stage & 1) ? bl0 : bl1;

        if (stage + 1 < NSG) {
            const int kbs = kbg + (stage + 1) * KC;
#pragma unroll
            for (int i = 0; i < 4; i++)
                bf4[i] = *reinterpret_cast<const float4*>(
                    W + (size_t)brow[i] * D_DIM + kbs + bc4[i] * 4);
        }

#pragma unroll
        for (int ks = 0; ks < 4; ks++) {
            const int g = stage * 4 + ks;
            const int slot = g & 1;

            uint32_t bhf[8][2], blf[8][2];
            const uint32_t kpart = ((uint32_t)(ks << 5) | (uint32_t)(jp << 4)) ^ xorTerm;
#pragma unroll
            for (int q = 0; q < 8; q += 2) {
                uint32_t ah_ = curh + (uint32_t)(q * 1024) + lanePart + kpart;
                uint32_t al_ = curl + (uint32_t)(q * 1024) + lanePart + kpart;
                LDSM_X4(bhf[q][0], bhf[q][1], bhf[q + 1][0], bhf[q + 1][1], ah_);
                LDSM_X4(blf[q][0], blf[q][1], blf[q + 1][0], blf[q + 1][1], al_);
            }

            uint32_t ah[4], al[4];
#pragma unroll
            for (int jj = 0; jj < 4; jj++)
                split2(af[slot][jj], ah[jj], al[jj]);

            if (g + 2 < NKG) LOAD_A(slot, g + 2);

#pragma unroll
            for (int nt = 0; nt < 8; nt++) {
                MMA16816(acc[nt], ah[0], ah[2], ah[1], ah[3], bhf[nt][0], bhf[nt][1]);
                MMA16816(acc[nt], ah[0], ah[2], ah[1], ah[3], blf[nt][0], blf[nt][1]);
                MMA16816(acc[nt], al[0], al[2], al[1], al[3], bhf[nt][0], bhf[nt][1]);
            }
        }

        if (stage + 1 < NSG) {
#pragma unroll
            for (int i = 0; i < 4; i++) {
                uint32_t h0, l0, h1, l1;
                split2(make_float2(bf4[i].x, bf4[i].y), h0, l0);
                split2(make_float2(bf4[i].z, bf4[i].w), h1, l1);
                uint32_t off = bswz(brow[i], (uint32_t)(bc4[i] * 8));
                asm volatile("st.shared.v2.b32 [%0], {%1,%2};" :: "r"(nxth + off), "r"(h0), "r"(h1) : "memory");
                asm volatile("st.shared.v2.b32 [%0], {%1,%2};" :: "r"(nxtl + off), "r"(l0), "r"(l1) : "memory");
            }
        }
        __syncthreads();
    }

    // ---- combine groups: warps 8-15 dump acc to smem, warps 0-7 add ----
    // red area reuses B buffers: warp wg slot = base + wg*4096 + lane*128 (32 floats)
    if (gi == 1) {
        uint32_t dst = base + (uint32_t)(wg * 4096 + lane * 128);
#pragma unroll
        for (int nt = 0; nt < 8; nt++) {
            asm volatile("st.shared.v4.b32 [%0], {%1,%2,%3,%4};" ::
                         "r"(dst + nt * 16),
                         "f"(acc[nt][0]), "f"(acc[nt][1]),
                         "f"(acc[nt][2]), "f"(acc[nt][3]) : "memory");
        }
    }
    __syncthreads();

    if (gi == 0) {
        uint32_t src = base + (uint32_t)(wg * 4096 + lane * 128);
#pragma unroll
        for (int nt = 0; nt < 8; nt++) {
            float r0, r1, r2, r3;
            asm volatile("ld.shared.v4.b32 {%0,%1,%2,%3}, [%4];"
                         : "=f"(r0), "=f"(r1), "=f"(r2), "=f"(r3)
                         : "r"(src + nt * 16));
            acc[nt][0] += r0; acc[nt][1] += r1;
            acc[nt][2] += r2; acc[nt][3] += r3;
        }

        float* sbase = g_scratch + (size_t)kh * NTOK * E_DIM;
#pragma unroll
        for (int nt = 0; nt < 8; nt++) {
            int col = nt * 8 + 2 * tr;
            *reinterpret_cast<float2*>(sbase + (size_t)rA * E_DIM + col) =
                make_float2(acc[nt][0], acc[nt][1]);
            *reinterpret_cast<float2*>(sbase + (size_t)(rA + 8) * E_DIM + col) =
                make_float2(acc[nt][2], acc[nt][3]);
        }
    }
}

// ---- combine K-halves + bias + top-2 + softmax: 4 lanes per token ----
__global__ __launch_bounds__(256, 4)
void moirai_topk_kernel(const float* __restrict__ b,
                        float* __restrict__ out)
{
    const int gid  = blockIdx.x * 256 + threadIdx.x;
    const int tok  = gid >> 2;
    const int r    = gid & 3;

    const float* r0 = g_scratch + (size_t)tok * E_DIM + r * 16;
    const float* r1 = g_scratch + ((size_t)NTOK + tok) * E_DIM + r * 16;
    const float* bb = b + r * 16;

    float v1 = -CUDART_INF_F, v2 = -CUDART_INF_F;
    int i1 = 0, i2 = 0;
#pragma unroll
    for (int g = 0; g < 4; g++) {
        float4 a  = *reinterpret_cast<const float4*>(r0 + g * 4);
        float4 c  = *reinterpret_cast<const float4*>(r1 + g * 4);
        float4 bv = *reinterpret_cast<const float4*>(bb + g * 4);
        float v[4] = {a.x + c.x + bv.x, a.y + c.y + bv.y,
                      a.z + c.z + bv.z, a.w + c.w + bv.w};
#pragma unroll
        for (int jj = 0; jj < 4; jj++) {
            int e = r * 16 + g * 4 + jj;
            if (v[jj] > v1)      { v2 = v1; i2 = i1; v1 = v[jj]; i1 = e; }
            else if (v[jj] > v2) { v2 = v[jj]; i2 = e; }
        }
    }

#pragma unroll
    for (int m = 1; m <= 2; m <<= 1) {
        float V1 = __shfl_xor_sync(0xFFFFFFFFu, v1, m);
        float V2 = __shfl_xor_sync(0xFFFFFFFFu, v2, m);
        int   I1 = __shfl_xor_sync(0xFFFFFFFFu, i1, m);
        int   I2 = __shfl_xor_sync(0xFFFFFFFFu, i2, m);
        if (V1 > v1 || (V1 == v1 && I1 < i1)) {
            float tv; int ti;
            tv = v1; v1 = V1; V1 = tv;  ti = i1; i1 = I1; I1 = ti;
            tv = v2; v2 = V2; V2 = tv;  ti = i2; i2 = I2; I2 = ti;
        }
        if (V1 > v2 || (V1 == v2 && I1 < i2)) { v2 = V1; i2 = I1; }
    }

    if (r == 0) {
        float ex  = expf(v2 - v1);
        float inv = 1.0f / (1.0f + ex);
        out[tok * 2 + 0] = inv;
        out[tok * 2 + 1] = ex * inv;
        float* idx_out = out + (size_t)NTOK * 2;
        idx_out[tok * 2 + 0] = (float)i1;
        idx_out[tok * 2 + 1] = (float)i2;
    }
}

extern "C" void kernel_launch(void* const* d_in, const int* in_sizes, int n_in,
                              void* d_out, int out_size)
{
    const float* x = (const float*)d_in[0];
    const float* W = (const float*)d_in[1];
    const float* b = (const float*)d_in[2];
    float* out = (float*)d_out;

    cudaFuncSetAttribute(moirai_gemm_kernel,
                         cudaFuncAttributeMaxDynamicSharedMemorySize, SMEM_ALLOC);
    moirai_gemm_kernel<<<128, 512, SMEM_ALLOC>>>(x, W);
    moirai_topk_kernel<<<(NTOK * 4) / 256, 256>>>(b, out);
}